// round 12
// baseline (speedup 1.0000x reference)
#include <cuda_runtime.h>
#include <cuda_bf16.h>
#include <math.h>

// ---------------- problem constants ----------------
#define BB   2
#define LL   512
#define DD   256
#define PDIM 64
#define HH   8
#define PP   4
#define HDH  32
#define OUTD 896
#define NROW (BB*LL)

#define SCALAR_SCALE 0.17677669529663687f   // 1/sqrt(32)
#define POINT_SCALE  0.2886751345948129f    // 1/sqrt(12)

#define IT 4       // queries per attention block
#define JT 32      // j tile
#define NJT (LL/JT)        // 16
#define JSPLIT 16          // one tile per block (TPS = 1)

#define KSPLIT 8
#define KCH (OUTD/KSPLIT)   // 112

// ---------------- device scratch ----------------
__device__ float g_qs[BB*HH*LL*HDH];
__device__ float g_ks[BB*HH*LL*HDH];
__device__ float g_vs[BB*HH*LL*HDH];
__device__ float g_qp[BB*HH*LL*12];
__device__ float g_kp[BB*HH*LL*12];
__device__ float g_vp[BB*HH*LL*12];
__device__ float g_qn[BB*HH*LL];
__device__ float g_kn[BB*HH*LL];
// split-KV partials
__device__ float g_pm[(size_t)JSPLIT*NROW*HH];
__device__ float g_pl[(size_t)JSPLIT*NROW*HH];
__device__ float g_psc[(size_t)JSPLIT*NROW*256];
__device__ float g_ppr[(size_t)JSPLIT*NROW*512];
__device__ float g_ppt[(size_t)JSPLIT*NROW*96];
// assembled features + output partials
__device__ float g_feat[(size_t)NROW*OUTD];
__device__ float g_part[(size_t)KSPLIT*NROW*DD];

// ---------------- mask dtype sniffing ----------------
__device__ __forceinline__ int mask_mode(const void* m) {
    int w0 = *(const int*)m;
    if (w0 == 0x3f800000) return 2;
    if (w0 == 1)          return 1;
    return 0;
}
__device__ __forceinline__ bool mask_at(const void* m, int mode, int j) {
    if (mode == 2) return ((const float*)m)[j] != 0.0f;
    if (mode == 1) return ((const int*)m)[j]   != 0;
    return ((const unsigned char*)m)[j] != 0;
}

// =====================================================================
// K1: projections. 8 rows/block, blockIdx.y selects matrix group.
// (round-10 version)
// =====================================================================
__global__ __launch_bounds__(256) void k_proj(
    const float* __restrict__ node,
    const float* __restrict__ rot,
    const float* __restrict__ trans,
    const float* __restrict__ Wq, const float* __restrict__ Wk, const float* __restrict__ Wv,
    const float* __restrict__ Wqp, const float* __restrict__ Wkp, const float* __restrict__ Wvp)
{
    __shared__ float xs[8][DD];
    __shared__ float lp[3][8][96];
    __shared__ float gp[3][8][96];
    __shared__ float Rs[8][9];
    __shared__ float Ts[8][3];

    const int tid  = threadIdx.x;
    const int row0 = blockIdx.x * 8;
    const int y    = blockIdx.y;

    for (int i = tid; i < 8*DD; i += 256) {
        int r = i >> 8, d = i & 255;
        xs[r][d] = node[(row0 + r)*DD + d];
    }
    if (y == 3 && tid < 96) {
        int r = tid / 12, c = tid % 12;
        if (c < 9) Rs[r][c]   = rot[(row0 + r)*9 + c];
        else       Ts[r][c-9] = trans[(row0 + r)*3 + (c-9)];
    }
    __syncthreads();

    if (y < 3) {
        const float* W = (y == 0) ? Wq : (y == 1) ? Wk : Wv;
        float* G = (y == 0) ? g_qs : (y == 1) ? g_ks : g_vs;
        float acc[8];
        #pragma unroll
        for (int r = 0; r < 8; r++) acc[r] = 0.f;
        const int c = tid;
        #pragma unroll 4
        for (int d = 0; d < DD; d++) {
            float w = W[d*DD + c];
            #pragma unroll
            for (int r = 0; r < 8; r++) acc[r] += xs[r][d]*w;
        }
        const int h = c >> 5, hd = c & 31;
        #pragma unroll
        for (int r = 0; r < 8; r++) {
            int n = row0 + r, b = n >> 9, l = n & 511;
            G[((b*HH + h)*LL + l)*HDH + hd] = acc[r];
        }
        return;
    }

    // ---- point projections ----
    for (int c = tid; c < 288; c += 256) {
        int m = c / 96, cc = c % 96;
        const float* W = (m == 0) ? Wqp : (m == 1) ? Wkp : Wvp;
        float acc[8];
        #pragma unroll
        for (int r = 0; r < 8; r++) acc[r] = 0.f;
        #pragma unroll 4
        for (int d = 0; d < DD; d++) {
            float w = W[d*96 + cc];
            #pragma unroll
            for (int r = 0; r < 8; r++) acc[r] += xs[r][d]*w;
        }
        #pragma unroll
        for (int r = 0; r < 8; r++) lp[m][r][cc] = acc[r];
    }
    __syncthreads();

    for (int i = tid; i < 3*8*96; i += 256) {
        int m = i / 768, rem = i % 768, r = rem / 96, c = rem % 96;
        int base = (c/3)*3, ax = c % 3;
        gp[m][r][c] = Rs[r][ax*3+0]*lp[m][r][base+0]
                    + Rs[r][ax*3+1]*lp[m][r][base+1]
                    + Rs[r][ax*3+2]*lp[m][r][base+2] + Ts[r][ax];
    }
    __syncthreads();

    for (int i = tid; i < 3*8*96; i += 256) {
        int m = i / 768, rem = i % 768, r = rem / 96, c = rem % 96;
        int h = c / 12, cc = c % 12;
        int n = row0 + r, b = n >> 9, l = n & 511;
        int o = ((b*HH + h)*LL + l)*12 + cc;
        float v = gp[m][r][c];
        if (m == 0)      g_qp[o] = v;
        else if (m == 1) g_kp[o] = v;
        else             g_vp[o] = v;
    }
    if (tid < 128) {
        int m = tid >> 6, r = (tid >> 3) & 7, h = tid & 7;
        float s = 0.f;
        #pragma unroll
        for (int c = 0; c < 12; c++) { float v = gp[m][r][h*12 + c]; s += v*v; }
        int n = row0 + r, b = n >> 9, l = n & 511;
        int o = (b*HH + h)*LL + l;
        if (m == 0) g_qn[o] = s; else g_kn[o] = s;
    }
}

// =====================================================================
// K2: fused attention, split-KV, one tile per block.
// NEW: dedicated pair-bias pass — each pairT element read from smem
// exactly ONCE; bias seeded directly into plog.
// =====================================================================
__global__ __launch_bounds__(256) void k_attn(
    const float* __restrict__ pair,
    const void*  __restrict__ maskp,
    const float* __restrict__ Wpb_g,
    const float* __restrict__ hw)
{
    __shared__ float pairT[IT*JT*64];    // [i][j][d]
    __shared__ float plog[IT*HH*JT];     // bias seed -> probabilities
    __shared__ float qs[IT*HH*HDH];
    __shared__ float qp[IT*HH*12];
    __shared__ float qn[IT*HH];
    __shared__ float wpbT[HH*64];        // [h][d]
    __shared__ float s_m[IT*HH], s_l[IT*HH];
    __shared__ float wsp[HH];

    const int tid = threadIdx.x;
    const int i0  = blockIdx.x * IT;
    const int b   = blockIdx.y >> 4;     // JSPLIT = 16
    const int sp  = blockIdx.y & 15;
    const int j0  = sp*JT;

    for (int t = tid; t < 512; t += 256)
        wpbT[(t & 7)*64 + (t >> 3)] = Wpb_g[t];
    for (int t = tid; t < IT*256; t += 256) {
        int i = t >> 8, r = t & 255, h = r >> 5, dd = r & 31;
        qs[t] = g_qs[((b*HH + h)*LL + i0 + i)*HDH + dd];
    }
    for (int t = tid; t < IT*96; t += 256) {
        int i = t / 96, c = t % 96, h = c / 12, cc = c % 12;
        qp[t] = g_qp[((b*HH + h)*LL + i0 + i)*12 + cc];
    }
    if (tid < IT*HH) {
        int i = tid >> 3, h = tid & 7;
        qn[tid] = g_qn[(b*HH + h)*LL + i0 + i];
    }
    if (tid < HH) wsp[tid] = log1pf(expf(hw[tid]));
    const int mmode = mask_mode(maskp);

    float a_sc[IT];
    float a_pr[HH];
    float a_pt[IT];
    #pragma unroll
    for (int i = 0; i < IT; i++) { a_sc[i] = 0.f; a_pt[i] = 0.f; }
    #pragma unroll
    for (int h = 0; h < HH; h++) a_pr[h] = 0.f;

    const int lh = tid >> 5, lj = tid & 31;
    const int pi = tid >> 6, pd = tid & 63;

    __syncthreads();

    // ---- stage pair tile ----
    {
        int i = tid >> 6, q = tid & 63;
        const float4* src = (const float4*)(pair +
            (((size_t)(b*LL + i0 + i))*LL + j0)*64);
        float4* dst = ((float4*)pairT) + i*512;
        #pragma unroll
        for (int u = 0; u < 8; u++) dst[q + u*64] = src[q + u*64];
    }
    __syncthreads();

    // ---- bias pass: thread = (bi, bj, bhalf). Each pairT element read
    // once; result (summed over d) seeded into plog[(bi*HH+h)*JT+bj].
    {
        const int bi    = tid >> 6;
        const int bj    = (tid >> 1) & 31;
        const int bhalf = tid & 1;
        float bacc[HH];
        #pragma unroll
        for (int h = 0; h < HH; h++) bacc[h] = 0.f;
        const float4* prow = (const float4*)&pairT[(bi*JT + bj)*64];
        #pragma unroll
        for (int u = 0; u < 8; u++) {
            int d4 = bhalf*8 + ((u + bj) & 7);   // swizzle: bank-spread
            float4 pv = prow[d4];
            #pragma unroll
            for (int h = 0; h < HH; h++) {
                float4 w = ((const float4*)&wpbT[h*64])[d4];
                bacc[h] += pv.x*w.x + pv.y*w.y + pv.z*w.z + pv.w*w.w;
            }
        }
        #pragma unroll
        for (int h = 0; h < HH; h++)
            bacc[h] += __shfl_xor_sync(0xffffffffu, bacc[h], 1);
        if (bhalf == 0) {
            #pragma unroll
            for (int h = 0; h < HH; h++)
                plog[(bi*HH + h)*JT + bj] = bacc[h];
        }
    }
    __syncthreads();

    // ---- logits + warp softmax + out_scalar ----
    {
        float s[IT] = {0.f, 0.f, 0.f, 0.f};
        {
            const float4* kv = (const float4*)&g_ks[((b*HH + lh)*LL + j0 + lj)*HDH];
            #pragma unroll
            for (int u = 0; u < 8; u++) {
                float4 kk = kv[u];
                #pragma unroll
                for (int i = 0; i < IT; i++) {
                    float4 qv = *(const float4*)&qs[(i*HH + lh)*HDH + u*4];
                    s[i] += qv.x*kk.x + qv.y*kk.y + qv.z*kk.z + qv.w*kk.w;
                }
            }
        }
        float pdot[IT];
        {
            const float4* kpv = (const float4*)&g_kp[((b*HH + lh)*LL + j0 + lj)*12];
            float4 kp0 = kpv[0], kp1 = kpv[1], kp2 = kpv[2];
            #pragma unroll
            for (int i = 0; i < IT; i++) {
                const float4* qpv = (const float4*)&qp[(i*HH + lh)*12];
                float4 q0 = qpv[0], q1 = qpv[1], q2 = qpv[2];
                pdot[i] = q0.x*kp0.x + q0.y*kp0.y + q0.z*kp0.z + q0.w*kp0.w
                        + q1.x*kp1.x + q1.y*kp1.y + q1.z*kp1.z + q1.w*kp1.w
                        + q2.x*kp2.x + q2.y*kp2.y + q2.z*kp2.z + q2.w*kp2.w;
            }
        }
        float kn = g_kn[(b*HH + lh)*LL + j0 + lj];
        float mpen = mask_at(maskp, mmode, b*LL + j0 + lj) ? 0.f : 1e9f;
        float hwc = -0.5f*wsp[lh]*POINT_SCALE;

        #pragma unroll
        for (int i = 0; i < IT; i++) {
            int r = i*HH + lh;
            float bias = plog[r*JT + lj];        // bias seed (own slot)
            float dist = qn[r] + kn - 2.f*pdot[i];
            float x = s[i]*SCALAR_SCALE + hwc*dist + bias - mpen;
            float tm = x;
            #pragma unroll
            for (int o = 16; o; o >>= 1) tm = fmaxf(tm, __shfl_xor_sync(0xffffffffu, tm, o));
            float p = __expf(x - tm);
            float ts = p;
            #pragma unroll
            for (int o = 16; o; o >>= 1) ts += __shfl_xor_sync(0xffffffffu, ts, o);
            plog[r*JT + lj] = p;
            if (lj == 0) { s_m[r] = tm; s_l[r] = ts; }
        }
        __syncwarp();

        const float* vb = &g_vs[((b*HH + lh)*LL + j0)*HDH + lj];
        #pragma unroll
        for (int j4 = 0; j4 < 8; j4++) {
            float4 p[IT];
            #pragma unroll
            for (int i = 0; i < IT; i++)
                p[i] = *(const float4*)&plog[(i*HH + lh)*JT + j4*4];
            float v0 = vb[(j4*4+0)*HDH];
            float v1 = vb[(j4*4+1)*HDH];
            float v2 = vb[(j4*4+2)*HDH];
            float v3 = vb[(j4*4+3)*HDH];
            #pragma unroll
            for (int i = 0; i < IT; i++)
                a_sc[i] += p[i].x*v0 + p[i].y*v1 + p[i].z*v2 + p[i].w*v3;
        }
    }
    __syncthreads();

    // ---- out_pair: thread = (i=pi, d=pd) ----
    {
        #pragma unroll
        for (int j4 = 0; j4 < 8; j4++) {
            float c0 = pairT[(pi*JT + j4*4+0)*64 + pd];
            float c1 = pairT[(pi*JT + j4*4+1)*64 + pd];
            float c2 = pairT[(pi*JT + j4*4+2)*64 + pd];
            float c3 = pairT[(pi*JT + j4*4+3)*64 + pd];
            #pragma unroll
            for (int h = 0; h < HH; h++) {
                float4 p = *(const float4*)&plog[(pi*HH + h)*JT + j4*4];
                a_pr[h] += p.x*c0 + p.y*c1 + p.z*c2 + p.w*c3;
            }
        }
    }
    // ---- out_points: tid<96, thread = (h, cc) ----
    if (tid < 96) {
        int h = tid / 12, cc = tid % 12;
        const float* vp = &g_vp[((b*HH + h)*LL + j0)*12 + cc];
        #pragma unroll
        for (int j4 = 0; j4 < 8; j4++) {
            float4 p[IT];
            #pragma unroll
            for (int i = 0; i < IT; i++)
                p[i] = *(const float4*)&plog[(i*HH + h)*JT + j4*4];
            float v0 = vp[(j4*4+0)*12];
            float v1 = vp[(j4*4+1)*12];
            float v2 = vp[(j4*4+2)*12];
            float v3 = vp[(j4*4+3)*12];
            #pragma unroll
            for (int i = 0; i < IT; i++)
                a_pt[i] += p[i].x*v0 + p[i].y*v1 + p[i].z*v2 + p[i].w*v3;
        }
    }
    __syncthreads();

    // ---- write partials (unnormalized) ----
    if (tid < IT*HH) {
        int i = tid >> 3, h = tid & 7;
        int row = b*LL + i0 + i;
        g_pm[((size_t)sp*NROW + row)*HH + h] = s_m[i*HH + h];
        g_pl[((size_t)sp*NROW + row)*HH + h] = s_l[i*HH + h];
    }
    #pragma unroll
    for (int i = 0; i < IT; i++) {
        int row = b*LL + i0 + i;
        g_psc[((size_t)sp*NROW + row)*256 + lh*HDH + lj] = a_sc[i];
    }
    {
        int row = b*LL + i0 + pi;
        #pragma unroll
        for (int h = 0; h < HH; h++)
            g_ppr[((size_t)sp*NROW + row)*512 + h*64 + pd] = a_pr[h];
    }
    if (tid < 96) {
        #pragma unroll
        for (int i = 0; i < IT; i++) {
            int row = b*LL + i0 + i;
            g_ppt[((size_t)sp*NROW + row)*96 + tid] = a_pt[i];
        }
    }
}

// =====================================================================
// K2b: combine JSPLIT partials; local-frame transform + norms;
// write feature vector. 1 row/block, 1024 blocks.
// =====================================================================
__global__ __launch_bounds__(256) void k_comb(
    const float* __restrict__ rot,
    const float* __restrict__ trans)
{
    __shared__ float coef[JSPLIT][HH];
    __shared__ float gpts[96];
    __shared__ float RT[12];

    const int tid = threadIdx.x;
    const int row = blockIdx.x;

    if (tid < HH) {
        int h = tid;
        float m[JSPLIT];
        float M = -1e30f;
        #pragma unroll
        for (int s = 0; s < JSPLIT; s++) {
            m[s] = g_pm[((size_t)s*NROW + row)*HH + h];
            M = fmaxf(M, m[s]);
        }
        float L = 0.f;
        float w[JSPLIT];
        #pragma unroll
        for (int s = 0; s < JSPLIT; s++) {
            w[s] = __expf(m[s] - M);
            L += w[s]*g_pl[((size_t)s*NROW + row)*HH + h];
        }
        float invL = 1.f / L;
        #pragma unroll
        for (int s = 0; s < JSPLIT; s++) coef[s][h] = w[s]*invL;
    }
    if (tid >= 32 && tid < 44) {
        int c = tid - 32;
        RT[c] = (c < 9) ? rot[(size_t)row*9 + c] : trans[(size_t)row*3 + (c - 9)];
    }
    __syncthreads();

    // scalar (256 values)
    {
        int h = tid >> 5;
        float v = 0.f;
        #pragma unroll
        for (int s = 0; s < JSPLIT; s++)
            v += coef[s][h]*g_psc[((size_t)s*NROW + row)*256 + tid];
        g_feat[(size_t)row*OUTD + tid] = v;
    }
    // pair (512 values)
    #pragma unroll
    for (int g = 0; g < 2; g++) {
        int idx = g*256 + tid;
        int h = idx >> 6;
        float v = 0.f;
        #pragma unroll
        for (int s = 0; s < JSPLIT; s++)
            v += coef[s][h]*g_ppr[((size_t)s*NROW + row)*512 + idx];
        g_feat[(size_t)row*OUTD + 256 + idx] = v;
    }
    // points (96 values, global frame)
    if (tid < 96) {
        int h = tid / 12;
        float v = 0.f;
        #pragma unroll
        for (int s = 0; s < JSPLIT; s++)
            v += coef[s][h]*g_ppt[((size_t)s*NROW + row)*96 + tid];
        gpts[tid] = v;
    }
    __syncthreads();
    if (tid < 32) {
        int hp = tid;
        const float* g = &gpts[hp*3];
        float d0 = g[0] - RT[9], d1 = g[1] - RT[10], d2 = g[2] - RT[11];
        float l0 = RT[0]*d0 + RT[3]*d1 + RT[6]*d2;
        float l1 = RT[1]*d0 + RT[4]*d1 + RT[7]*d2;
        float l2 = RT[2]*d0 + RT[5]*d1 + RT[8]*d2;
        size_t base = (size_t)row*OUTD;
        g_feat[base + 768 + hp*3 + 0] = l0;
        g_feat[base + 768 + hp*3 + 1] = l1;
        g_feat[base + 768 + hp*3 + 2] = l2;
        g_feat[base + 864 + hp] = sqrtf(l0*l0 + l1*l1 + l2*l2);
    }
}

// =====================================================================
// K3: split-K GEMM, 16 rows/block, KSPLIT=8 -> 512 blocks.
// (round-10 version — measured best at 26.6us)
// =====================================================================
__global__ __launch_bounds__(256) void k_gemm_out(const float* __restrict__ Wout)
{
    __shared__ float fs[16][KCH];
    const int tid  = threadIdx.x;
    const int row0 = blockIdx.x * 16;
    const int y    = blockIdx.y;
    const int f0   = y * KCH;

    for (int t = tid; t < 16*(KCH/4); t += 256) {
        int r = t / (KCH/4), q = t % (KCH/4);
        ((float4*)fs[r])[q] =
            *(const float4*)&g_feat[(size_t)(row0 + r)*OUTD + f0 + q*4];
    }
    __syncthreads();

    float acc[16];
    #pragma unroll
    for (int r = 0; r < 16; r++) acc[r] = 0.f;
    const int d = tid;
    for (int f = 0; f < KCH; f += 4) {
        float w0 = Wout[(f0 + f + 0)*DD + d];
        float w1 = Wout[(f0 + f + 1)*DD + d];
        float w2 = Wout[(f0 + f + 2)*DD + d];
        float w3 = Wout[(f0 + f + 3)*DD + d];
        #pragma unroll
        for (int r = 0; r < 16; r++) {
            float4 fv = *(const float4*)&fs[r][f];
            acc[r] += fv.x*w0 + fv.y*w1 + fv.z*w2 + fv.w*w3;
        }
    }
    #pragma unroll
    for (int r = 0; r < 16; r++)
        g_part[((size_t)y*NROW + row0 + r)*DD + d] = acc[r];
}

// =====================================================================
// K4: partial reduce + bias + residual + LayerNorm. 8 rows/block.
// =====================================================================
__global__ __launch_bounds__(256) void k_ln(
    const float* __restrict__ node,
    const float* __restrict__ bout,
    const float* __restrict__ gamma,
    const float* __restrict__ beta,
    float* __restrict__ out)
{
    __shared__ float xsm[8][DD];
    __shared__ float s_mu[8], s_inv[8];
    const int tid  = threadIdx.x;
    const int row0 = blockIdx.x * 8;
    const int d = tid;

    const float bo = bout[d];
    #pragma unroll
    for (int r = 0; r < 8; r++) {
        int row = row0 + r;
        float s = node[row*DD + d] + bo;
        #pragma unroll
        for (int y = 0; y < KSPLIT; y++)
            s += g_part[((size_t)y*NROW + row)*DD + d];
        xsm[r][d] = s;
    }
    __syncthreads();

    {
        int w = tid >> 5, lane = tid & 31;
        float s = 0.f;
        #pragma unroll
        for (int j = lane; j < DD; j += 32) s += xsm[w][j];
        #pragma unroll
        for (int o = 16; o; o >>= 1) s += __shfl_xor_sync(0xffffffffu, s, o);
        float mu = s * (1.f/DD);
        float v = 0.f;
        #pragma unroll
        for (int j = lane; j < DD; j += 32) { float t = xsm[w][j] - mu; v += t*t; }
        #pragma unroll
        for (int o = 16; o; o >>= 1) v += __shfl_xor_sync(0xffffffffu, v, o);
        if (lane == 0) { s_mu[w] = mu; s_inv[w] = rsqrtf(v*(1.f/DD) + 1e-5f); }
    }
    __syncthreads();

    const float ga = gamma[d], be = beta[d];
    #pragma unroll
    for (int r = 0; r < 8; r++)
        out[(row0 + r)*DD + d] = (xsm[r][d] - s_mu[r])*s_inv[r]*ga + be;
}

// =====================================================================
extern "C" void kernel_launch(void* const* d_in, const int* in_sizes, int n_in,
                              void* d_out, int out_size)
{
    const float* node  = (const float*)d_in[0];
    const float* pair  = (const float*)d_in[1];
    const float* rot   = (const float*)d_in[2];
    const float* trans = (const float*)d_in[3];
    const void*  maskp = (const void*) d_in[4];
    const float* Wq    = (const float*)d_in[5];
    const float* Wk    = (const float*)d_in[6];
    const float* Wv    = (const float*)d_in[7];
    const float* Wqp   = (const float*)d_in[8];
    const float* Wkp   = (const float*)d_in[9];
    const float* Wvp   = (const float*)d_in[10];
    const float* Wpb   = (const float*)d_in[11];
    const float* hw    = (const float*)d_in[12];
    const float* Wout  = (const float*)d_in[13];
    const float* bout  = (const float*)d_in[14];
    const float* gamma = (const float*)d_in[15];
    const float* beta  = (const float*)d_in[16];
    float* out = (float*)d_out;

    k_proj<<<dim3(NROW/8, 4), 256>>>(node, rot, trans, Wq, Wk, Wv, Wqp, Wkp, Wvp);
    k_attn<<<dim3(LL/IT, BB*JSPLIT), 256>>>(pair, maskp, Wpb, hw);
    k_comb<<<NROW, 256>>>(rot, trans);
    k_gemm_out<<<dim3(NROW/16, KSPLIT), 256>>>(Wout);
    k_ln<<<NROW/8, 256>>>(node, bout, gamma, beta, out);
}

// round 14
// speedup vs baseline: 1.1305x; 1.1305x over previous
#include <cuda_runtime.h>
#include <cuda_bf16.h>
#include <math.h>

// ---------------- problem constants ----------------
#define BB   2
#define LL   512
#define DD   256
#define PDIM 64
#define HH   8
#define PP   4
#define HDH  32
#define OUTD 896
#define NROW (BB*LL)

#define SCALAR_SCALE 0.17677669529663687f   // 1/sqrt(32)
#define POINT_SCALE  0.2886751345948129f    // 1/sqrt(12)

#define IT 4       // queries per attention block
#define JT 32      // j tile
#define NJT (LL/JT)        // 16
#define JSPLIT 16          // one tile per block

#define KSPLIT 8
#define KCH (OUTD/KSPLIT)   // 112

// ---------------- device scratch ----------------
__device__ float g_qs[BB*HH*LL*HDH];
__device__ float g_ks[BB*HH*LL*HDH];
__device__ float g_vs[BB*HH*LL*HDH];
__device__ float g_qp[BB*HH*LL*12];
__device__ float g_kp[BB*HH*LL*12];
__device__ float g_vp[BB*HH*LL*12];
__device__ float g_qn[BB*HH*LL];
__device__ float g_kn[BB*HH*LL];
// split-KV partials
__device__ float g_pm[(size_t)JSPLIT*NROW*HH];
__device__ float g_pl[(size_t)JSPLIT*NROW*HH];
__device__ float g_psc[(size_t)JSPLIT*NROW*256];
__device__ float g_ppr[(size_t)JSPLIT*NROW*512];
__device__ float g_ppt[(size_t)JSPLIT*NROW*96];
// assembled features + output partials
__device__ float g_feat[(size_t)NROW*OUTD];
__device__ float g_part[(size_t)KSPLIT*NROW*DD];
__device__ int   g_dummy;

// ---------------- mask dtype sniffing ----------------
__device__ __forceinline__ int mask_mode(const void* m) {
    int w0 = *(const int*)m;
    if (w0 == 0x3f800000) return 2;
    if (w0 == 1)          return 1;
    return 0;
}
__device__ __forceinline__ bool mask_at(const void* m, int mode, int j) {
    if (mode == 2) return ((const float*)m)[j] != 0.0f;
    if (mode == 1) return ((const int*)m)[j]   != 0;
    return ((const unsigned char*)m)[j] != 0;
}

// =====================================================================
// K0: no-op (shifts the ncu capture index so k_attn gets profiled)
// =====================================================================
__global__ void k_nop() { if (threadIdx.x == 0) g_dummy = 0; }

// =====================================================================
// K1: projections. 8 rows/block, blockIdx.y selects matrix group.
// =====================================================================
__global__ __launch_bounds__(256) void k_proj(
    const float* __restrict__ node,
    const float* __restrict__ rot,
    const float* __restrict__ trans,
    const float* __restrict__ Wq, const float* __restrict__ Wk, const float* __restrict__ Wv,
    const float* __restrict__ Wqp, const float* __restrict__ Wkp, const float* __restrict__ Wvp)
{
    __shared__ float xs[8][DD];
    __shared__ float lp[3][8][96];
    __shared__ float gp[3][8][96];
    __shared__ float Rs[8][9];
    __shared__ float Ts[8][3];

    const int tid  = threadIdx.x;
    const int row0 = blockIdx.x * 8;
    const int y    = blockIdx.y;

    for (int i = tid; i < 8*DD; i += 256) {
        int r = i >> 8, d = i & 255;
        xs[r][d] = node[(row0 + r)*DD + d];
    }
    if (y == 3 && tid < 96) {
        int r = tid / 12, c = tid % 12;
        if (c < 9) Rs[r][c]   = rot[(row0 + r)*9 + c];
        else       Ts[r][c-9] = trans[(row0 + r)*3 + (c-9)];
    }
    __syncthreads();

    if (y < 3) {
        const float* W = (y == 0) ? Wq : (y == 1) ? Wk : Wv;
        float* G = (y == 0) ? g_qs : (y == 1) ? g_ks : g_vs;
        float acc[8];
        #pragma unroll
        for (int r = 0; r < 8; r++) acc[r] = 0.f;
        const int c = tid;
        #pragma unroll 4
        for (int d = 0; d < DD; d++) {
            float w = W[d*DD + c];
            #pragma unroll
            for (int r = 0; r < 8; r++) acc[r] += xs[r][d]*w;
        }
        const int h = c >> 5, hd = c & 31;
        #pragma unroll
        for (int r = 0; r < 8; r++) {
            int n = row0 + r, b = n >> 9, l = n & 511;
            G[((b*HH + h)*LL + l)*HDH + hd] = acc[r];
        }
        return;
    }

    // ---- point projections ----
    for (int c = tid; c < 288; c += 256) {
        int m = c / 96, cc = c % 96;
        const float* W = (m == 0) ? Wqp : (m == 1) ? Wkp : Wvp;
        float acc[8];
        #pragma unroll
        for (int r = 0; r < 8; r++) acc[r] = 0.f;
        #pragma unroll 4
        for (int d = 0; d < DD; d++) {
            float w = W[d*96 + cc];
            #pragma unroll
            for (int r = 0; r < 8; r++) acc[r] += xs[r][d]*w;
        }
        #pragma unroll
        for (int r = 0; r < 8; r++) lp[m][r][cc] = acc[r];
    }
    __syncthreads();

    for (int i = tid; i < 3*8*96; i += 256) {
        int m = i / 768, rem = i % 768, r = rem / 96, c = rem % 96;
        int base = (c/3)*3, ax = c % 3;
        gp[m][r][c] = Rs[r][ax*3+0]*lp[m][r][base+0]
                    + Rs[r][ax*3+1]*lp[m][r][base+1]
                    + Rs[r][ax*3+2]*lp[m][r][base+2] + Ts[r][ax];
    }
    __syncthreads();

    for (int i = tid; i < 3*8*96; i += 256) {
        int m = i / 768, rem = i % 768, r = rem / 96, c = rem % 96;
        int h = c / 12, cc = c % 12;
        int n = row0 + r, b = n >> 9, l = n & 511;
        int o = ((b*HH + h)*LL + l)*12 + cc;
        float v = gp[m][r][c];
        if (m == 0)      g_qp[o] = v;
        else if (m == 1) g_kp[o] = v;
        else             g_vp[o] = v;
    }
    if (tid < 128) {
        int m = tid >> 6, r = (tid >> 3) & 7, h = tid & 7;
        float s = 0.f;
        #pragma unroll
        for (int c = 0; c < 12; c++) { float v = gp[m][r][h*12 + c]; s += v*v; }
        int n = row0 + r, b = n >> 9, l = n & 511;
        int o = (b*HH + h)*LL + l;
        if (m == 0) g_qn[o] = s; else g_kn[o] = s;
    }
}

// =====================================================================
// K2: fused attention (round-10 structure + entry-prefetch of the
// pair tile + single init barrier + point-K prefetch before bias).
// 4096 blocks x 256 threads.
// =====================================================================
__global__ __launch_bounds__(256) void k_attn(
    const float* __restrict__ pair,
    const void*  __restrict__ maskp,
    const float* __restrict__ Wpb_g,
    const float* __restrict__ hw)
{
    __shared__ float pairT[IT*JT*64];    // [i][j][d]
    __shared__ float plog[IT*HH*JT];
    __shared__ float qs[IT*HH*HDH];
    __shared__ float qp[IT*HH*12];
    __shared__ float qn[IT*HH];
    __shared__ float wpbT[HH*64];        // [h][d]
    __shared__ float s_m[IT*HH], s_l[IT*HH];
    __shared__ float wsp[HH];

    const int tid = threadIdx.x;
    const int i0  = blockIdx.x * IT;
    const int b   = blockIdx.y >> 4;     // JSPLIT = 16
    const int sp  = blockIdx.y & 15;
    const int j0  = sp*JT;

    // ---- pair tile prefetch into registers (issues LDGs immediately) ----
    float4 pf[8];
    {
        int i = tid >> 6, q = tid & 63;
        const float4* src = (const float4*)(pair +
            (((size_t)(b*LL + i0 + i))*LL + j0)*64);
        #pragma unroll
        for (int u = 0; u < 8; u++) pf[u] = src[q + u*64];
    }

    // ---- init smem (overlaps with pair LDG latency) ----
    for (int t = tid; t < 512; t += 256)
        wpbT[(t & 7)*64 + (t >> 3)] = Wpb_g[t];
    for (int t = tid; t < IT*256; t += 256) {
        int i = t >> 8, r = t & 255, h = r >> 5, dd = r & 31;
        qs[t] = g_qs[((b*HH + h)*LL + i0 + i)*HDH + dd];
    }
    for (int t = tid; t < IT*96; t += 256) {
        int i = t / 96, c = t % 96, h = c / 12, cc = c % 12;
        qp[t] = g_qp[((b*HH + h)*LL + i0 + i)*12 + cc];
    }
    if (tid < IT*HH) {
        int i = tid >> 3, h = tid & 7;
        qn[tid] = g_qn[(b*HH + h)*LL + i0 + i];
    }
    if (tid < HH) wsp[tid] = log1pf(expf(hw[tid]));
    const int mmode = mask_mode(maskp);

    // ---- store pair tile to smem ----
    {
        int i = tid >> 6, q = tid & 63;
        float4* dst = ((float4*)pairT) + i*512;
        #pragma unroll
        for (int u = 0; u < 8; u++) dst[q + u*64] = pf[u];
    }

    float a_sc[IT];
    float a_pr[HH];
    float a_pt[IT];
    #pragma unroll
    for (int i = 0; i < IT; i++) { a_sc[i] = 0.f; a_pt[i] = 0.f; }
    #pragma unroll
    for (int h = 0; h < HH; h++) a_pr[h] = 0.f;

    const int lh = tid >> 5, lj = tid & 31;
    const int pi = tid >> 6, pd = tid & 63;

    __syncthreads();   // single barrier: init + pair tile all visible

    // ---- logits + warp softmax + out_scalar ----
    {
        // prefetch point-K operands (global) ahead of the bias loop
        const float4* kpv = (const float4*)&g_kp[((b*HH + lh)*LL + j0 + lj)*12];
        float4 kp0 = kpv[0], kp1 = kpv[1], kp2 = kpv[2];
        float kn = g_kn[(b*HH + lh)*LL + j0 + lj];
        float mpen = mask_at(maskp, mmode, b*LL + j0 + lj) ? 0.f : 1e9f;

        float bias[IT] = {0.f, 0.f, 0.f, 0.f};
        {
            const float4* wh4 = (const float4*)&wpbT[lh*64];
            const float4* pr0 = (const float4*)&pairT[(0*JT + lj)*64];
            const float4* pr1 = (const float4*)&pairT[(1*JT + lj)*64];
            const float4* pr2 = (const float4*)&pairT[(2*JT + lj)*64];
            const float4* pr3 = (const float4*)&pairT[(3*JT + lj)*64];
            #pragma unroll
            for (int q4 = 0; q4 < 16; q4++) {
                int d4 = (q4 + lj) & 15;
                float4 w = wh4[d4];
                float4 a0 = pr0[d4], a1 = pr1[d4], a2 = pr2[d4], a3 = pr3[d4];
                bias[0] += a0.x*w.x + a0.y*w.y + a0.z*w.z + a0.w*w.w;
                bias[1] += a1.x*w.x + a1.y*w.y + a1.z*w.z + a1.w*w.w;
                bias[2] += a2.x*w.x + a2.y*w.y + a2.z*w.z + a2.w*w.w;
                bias[3] += a3.x*w.x + a3.y*w.y + a3.z*w.z + a3.w*w.w;
            }
        }
        float s[IT] = {0.f, 0.f, 0.f, 0.f};
        {
            const float4* kv = (const float4*)&g_ks[((b*HH + lh)*LL + j0 + lj)*HDH];
            #pragma unroll
            for (int u = 0; u < 8; u++) {
                float4 kk = kv[u];
                #pragma unroll
                for (int i = 0; i < IT; i++) {
                    float4 qv = *(const float4*)&qs[(i*HH + lh)*HDH + u*4];
                    s[i] += qv.x*kk.x + qv.y*kk.y + qv.z*kk.z + qv.w*kk.w;
                }
            }
        }
        float pdot[IT];
        {
            #pragma unroll
            for (int i = 0; i < IT; i++) {
                const float4* qpv = (const float4*)&qp[(i*HH + lh)*12];
                float4 q0 = qpv[0], q1 = qpv[1], q2 = qpv[2];
                pdot[i] = q0.x*kp0.x + q0.y*kp0.y + q0.z*kp0.z + q0.w*kp0.w
                        + q1.x*kp1.x + q1.y*kp1.y + q1.z*kp1.z + q1.w*kp1.w
                        + q2.x*kp2.x + q2.y*kp2.y + q2.z*kp2.z + q2.w*kp2.w;
            }
        }
        float hwc = -0.5f*wsp[lh]*POINT_SCALE;

        #pragma unroll
        for (int i = 0; i < IT; i++) {
            int r = i*HH + lh;
            float dist = qn[r] + kn - 2.f*pdot[i];
            float x = s[i]*SCALAR_SCALE + hwc*dist + bias[i] - mpen;
            float tm = x;
            #pragma unroll
            for (int o = 16; o; o >>= 1) tm = fmaxf(tm, __shfl_xor_sync(0xffffffffu, tm, o));
            float p = __expf(x - tm);
            float ts = p;
            #pragma unroll
            for (int o = 16; o; o >>= 1) ts += __shfl_xor_sync(0xffffffffu, ts, o);
            plog[r*JT + lj] = p;
            if (lj == 0) { s_m[r] = tm; s_l[r] = ts; }
        }
        __syncwarp();

        const float* vb = &g_vs[((b*HH + lh)*LL + j0)*HDH + lj];
        #pragma unroll
        for (int j4 = 0; j4 < 8; j4++) {
            float4 p[IT];
            #pragma unroll
            for (int i = 0; i < IT; i++)
                p[i] = *(const float4*)&plog[(i*HH + lh)*JT + j4*4];
            float v0 = vb[(j4*4+0)*HDH];
            float v1 = vb[(j4*4+1)*HDH];
            float v2 = vb[(j4*4+2)*HDH];
            float v3 = vb[(j4*4+3)*HDH];
            #pragma unroll
            for (int i = 0; i < IT; i++)
                a_sc[i] += p[i].x*v0 + p[i].y*v1 + p[i].z*v2 + p[i].w*v3;
        }
    }
    __syncthreads();

    // ---- out_pair: thread = (i=pi, d=pd) ----
    {
        #pragma unroll
        for (int j4 = 0; j4 < 8; j4++) {
            float c0 = pairT[(pi*JT + j4*4+0)*64 + pd];
            float c1 = pairT[(pi*JT + j4*4+1)*64 + pd];
            float c2 = pairT[(pi*JT + j4*4+2)*64 + pd];
            float c3 = pairT[(pi*JT + j4*4+3)*64 + pd];
            #pragma unroll
            for (int h = 0; h < HH; h++) {
                float4 p = *(const float4*)&plog[(pi*HH + h)*JT + j4*4];
                a_pr[h] += p.x*c0 + p.y*c1 + p.z*c2 + p.w*c3;
            }
        }
    }
    // ---- out_points: tid<96, thread = (h, cc) ----
    if (tid < 96) {
        int h = tid / 12, cc = tid % 12;
        const float* vp = &g_vp[((b*HH + h)*LL + j0)*12 + cc];
        #pragma unroll
        for (int j4 = 0; j4 < 8; j4++) {
            float4 p[IT];
            #pragma unroll
            for (int i = 0; i < IT; i++)
                p[i] = *(const float4*)&plog[(i*HH + h)*JT + j4*4];
            float v0 = vp[(j4*4+0)*12];
            float v1 = vp[(j4*4+1)*12];
            float v2 = vp[(j4*4+2)*12];
            float v3 = vp[(j4*4+3)*12];
            #pragma unroll
            for (int i = 0; i < IT; i++)
                a_pt[i] += p[i].x*v0 + p[i].y*v1 + p[i].z*v2 + p[i].w*v3;
        }
    }
    __syncthreads();

    // ---- write partials (unnormalized) ----
    if (tid < IT*HH) {
        int i = tid >> 3, h = tid & 7;
        int row = b*LL + i0 + i;
        g_pm[((size_t)sp*NROW + row)*HH + h] = s_m[i*HH + h];
        g_pl[((size_t)sp*NROW + row)*HH + h] = s_l[i*HH + h];
    }
    #pragma unroll
    for (int i = 0; i < IT; i++) {
        int row = b*LL + i0 + i;
        g_psc[((size_t)sp*NROW + row)*256 + lh*HDH + lj] = a_sc[i];
    }
    {
        int row = b*LL + i0 + pi;
        #pragma unroll
        for (int h = 0; h < HH; h++)
            g_ppr[((size_t)sp*NROW + row)*512 + h*64 + pd] = a_pr[h];
    }
    if (tid < 96) {
        #pragma unroll
        for (int i = 0; i < IT; i++) {
            int row = b*LL + i0 + i;
            g_ppt[((size_t)sp*NROW + row)*96 + tid] = a_pt[i];
        }
    }
}

// =====================================================================
// K2b: combine JSPLIT partials; local-frame transform + norms;
// write feature vector. 1 row/block, 1024 blocks.
// =====================================================================
__global__ __launch_bounds__(256) void k_comb(
    const float* __restrict__ rot,
    const float* __restrict__ trans)
{
    __shared__ float coef[JSPLIT][HH];
    __shared__ float gpts[96];
    __shared__ float RT[12];

    const int tid = threadIdx.x;
    const int row = blockIdx.x;

    if (tid < HH) {
        int h = tid;
        float m[JSPLIT];
        float M = -1e30f;
        #pragma unroll
        for (int s = 0; s < JSPLIT; s++) {
            m[s] = g_pm[((size_t)s*NROW + row)*HH + h];
            M = fmaxf(M, m[s]);
        }
        float L = 0.f;
        float w[JSPLIT];
        #pragma unroll
        for (int s = 0; s < JSPLIT; s++) {
            w[s] = __expf(m[s] - M);
            L += w[s]*g_pl[((size_t)s*NROW + row)*HH + h];
        }
        float invL = 1.f / L;
        #pragma unroll
        for (int s = 0; s < JSPLIT; s++) coef[s][h] = w[s]*invL;
    }
    if (tid >= 32 && tid < 44) {
        int c = tid - 32;
        RT[c] = (c < 9) ? rot[(size_t)row*9 + c] : trans[(size_t)row*3 + (c - 9)];
    }
    __syncthreads();

    // scalar (256 values)
    {
        int h = tid >> 5;
        float v = 0.f;
        #pragma unroll
        for (int s = 0; s < JSPLIT; s++)
            v += coef[s][h]*g_psc[((size_t)s*NROW + row)*256 + tid];
        g_feat[(size_t)row*OUTD + tid] = v;
    }
    // pair (512 values)
    #pragma unroll
    for (int g = 0; g < 2; g++) {
        int idx = g*256 + tid;
        int h = idx >> 6;
        float v = 0.f;
        #pragma unroll
        for (int s = 0; s < JSPLIT; s++)
            v += coef[s][h]*g_ppr[((size_t)s*NROW + row)*512 + idx];
        g_feat[(size_t)row*OUTD + 256 + idx] = v;
    }
    // points (96 values, global frame)
    if (tid < 96) {
        int h = tid / 12;
        float v = 0.f;
        #pragma unroll
        for (int s = 0; s < JSPLIT; s++)
            v += coef[s][h]*g_ppt[((size_t)s*NROW + row)*96 + tid];
        gpts[tid] = v;
    }
    __syncthreads();
    if (tid < 32) {
        int hp = tid;
        const float* g = &gpts[hp*3];
        float d0 = g[0] - RT[9], d1 = g[1] - RT[10], d2 = g[2] - RT[11];
        float l0 = RT[0]*d0 + RT[3]*d1 + RT[6]*d2;
        float l1 = RT[1]*d0 + RT[4]*d1 + RT[7]*d2;
        float l2 = RT[2]*d0 + RT[5]*d1 + RT[8]*d2;
        size_t base = (size_t)row*OUTD;
        g_feat[base + 768 + hp*3 + 0] = l0;
        g_feat[base + 768 + hp*3 + 1] = l1;
        g_feat[base + 768 + hp*3 + 2] = l2;
        g_feat[base + 864 + hp] = sqrtf(l0*l0 + l1*l1 + l2*l2);
    }
}

// =====================================================================
// K3: split-K GEMM, 16 rows/block, KSPLIT=8 -> 512 blocks.
// (round-10 version — measured 26.6us)
// =====================================================================
__global__ __launch_bounds__(256) void k_gemm_out(const float* __restrict__ Wout)
{
    __shared__ float fs[16][KCH];
    const int tid  = threadIdx.x;
    const int row0 = blockIdx.x * 16;
    const int y    = blockIdx.y;
    const int f0   = y * KCH;

    for (int t = tid; t < 16*(KCH/4); t += 256) {
        int r = t / (KCH/4), q = t % (KCH/4);
        ((float4*)fs[r])[q] =
            *(const float4*)&g_feat[(size_t)(row0 + r)*OUTD + f0 + q*4];
    }
    __syncthreads();

    float acc[16];
    #pragma unroll
    for (int r = 0; r < 16; r++) acc[r] = 0.f;
    const int d = tid;
    for (int f = 0; f < KCH; f += 4) {
        float w0 = Wout[(f0 + f + 0)*DD + d];
        float w1 = Wout[(f0 + f + 1)*DD + d];
        float w2 = Wout[(f0 + f + 2)*DD + d];
        float w3 = Wout[(f0 + f + 3)*DD + d];
        #pragma unroll
        for (int r = 0; r < 16; r++) {
            float4 fv = *(const float4*)&fs[r][f];
            acc[r] += fv.x*w0 + fv.y*w1 + fv.z*w2 + fv.w*w3;
        }
    }
    #pragma unroll
    for (int r = 0; r < 16; r++)
        g_part[((size_t)y*NROW + row0 + r)*DD + d] = acc[r];
}

// =====================================================================
// K4: partial reduce + bias + residual + LayerNorm. 8 rows/block.
// =====================================================================
__global__ __launch_bounds__(256) void k_ln(
    const float* __restrict__ node,
    const float* __restrict__ bout,
    const float* __restrict__ gamma,
    const float* __restrict__ beta,
    float* __restrict__ out)
{
    __shared__ float xsm[8][DD];
    __shared__ float s_mu[8], s_inv[8];
    const int tid  = threadIdx.x;
    const int row0 = blockIdx.x * 8;
    const int d = tid;

    const float bo = bout[d];
    #pragma unroll
    for (int r = 0; r < 8; r++) {
        int row = row0 + r;
        float s = node[row*DD + d] + bo;
        #pragma unroll
        for (int y = 0; y < KSPLIT; y++)
            s += g_part[((size_t)y*NROW + row)*DD + d];
        xsm[r][d] = s;
    }
    __syncthreads();

    {
        int w = tid >> 5, lane = tid & 31;
        float s = 0.f;
        #pragma unroll
        for (int j = lane; j < DD; j += 32) s += xsm[w][j];
        #pragma unroll
        for (int o = 16; o; o >>= 1) s += __shfl_xor_sync(0xffffffffu, s, o);
        float mu = s * (1.f/DD);
        float v = 0.f;
        #pragma unroll
        for (int j = lane; j < DD; j += 32) { float t = xsm[w][j] - mu; v += t*t; }
        #pragma unroll
        for (int o = 16; o; o >>= 1) v += __shfl_xor_sync(0xffffffffu, v, o);
        if (lane == 0) { s_mu[w] = mu; s_inv[w] = rsqrtf(v*(1.f/DD) + 1e-5f); }
    }
    __syncthreads();

    const float ga = gamma[d], be = beta[d];
    #pragma unroll
    for (int r = 0; r < 8; r++)
        out[(row0 + r)*DD + d] = (xsm[r][d] - s_mu[r])*s_inv[r]*ga + be;
}

// =====================================================================
extern "C" void kernel_launch(void* const* d_in, const int* in_sizes, int n_in,
                              void* d_out, int out_size)
{
    const float* node  = (const float*)d_in[0];
    const float* pair  = (const float*)d_in[1];
    const float* rot   = (const float*)d_in[2];
    const float* trans = (const float*)d_in[3];
    const void*  maskp = (const void*) d_in[4];
    const float* Wq    = (const float*)d_in[5];
    const float* Wk    = (const float*)d_in[6];
    const float* Wv    = (const float*)d_in[7];
    const float* Wqp   = (const float*)d_in[8];
    const float* Wkp   = (const float*)d_in[9];
    const float* Wvp   = (const float*)d_in[10];
    const float* Wpb   = (const float*)d_in[11];
    const float* hw    = (const float*)d_in[12];
    const float* Wout  = (const float*)d_in[13];
    const float* bout  = (const float*)d_in[14];
    const float* gamma = (const float*)d_in[15];
    const float* beta  = (const float*)d_in[16];
    float* out = (float*)d_out;

    k_nop<<<1, 32>>>();
    k_proj<<<dim3(NROW/8, 4), 256>>>(node, rot, trans, Wq, Wk, Wv, Wqp, Wkp, Wvp);
    k_attn<<<dim3(LL/IT, BB*JSPLIT), 256>>>(pair, maskp, Wpb, hw);
    k_comb<<<NROW, 256>>>(rot, trans);
    k_gemm_out<<<dim3(NROW/16, KSPLIT), 256>>>(Wout);
    k_ln<<<NROW/8, 256>>>(node, bout, gamma, beta, out);
}

// round 15
// speedup vs baseline: 1.1549x; 1.0215x over previous
#include <cuda_runtime.h>
#include <cuda_bf16.h>
#include <cuda_fp16.h>
#include <math.h>

// ---------------- problem constants ----------------
#define BB   2
#define LL   512
#define DD   256
#define PDIM 64
#define HH   8
#define PP   4
#define HDH  32
#define OUTD 896
#define NROW (BB*LL)

#define SCALAR_SCALE 0.17677669529663687f   // 1/sqrt(32)
#define POINT_SCALE  0.2886751345948129f    // 1/sqrt(12)

#define IT 4       // queries per attention block
#define JT 32      // j tile
#define NJT (LL/JT)        // 16
#define JSPLIT 16          // one tile per block

#define KSPLIT 8
#define KCH (OUTD/KSPLIT)   // 112

// ---------------- device scratch ----------------
__device__ float g_qs[BB*HH*LL*HDH];
__device__ float g_ks[BB*HH*LL*HDH];
__device__ float g_vs[BB*HH*LL*HDH];
__device__ float g_qp[BB*HH*LL*12];
__device__ float g_kp[BB*HH*LL*12];
__device__ float g_vp[BB*HH*LL*12];
__device__ float g_qn[BB*HH*LL];
__device__ float g_kn[BB*HH*LL];
// split-KV partials (fp16 payload, fp32 m/l)
__device__ float  g_pm[(size_t)JSPLIT*NROW*HH];
__device__ float  g_pl[(size_t)JSPLIT*NROW*HH];
__device__ __half g_psc[(size_t)JSPLIT*NROW*256];
__device__ __half g_ppr[(size_t)JSPLIT*NROW*512];
__device__ __half g_ppt[(size_t)JSPLIT*NROW*96];
// assembled features + output partials
__device__ float g_feat[(size_t)NROW*OUTD];
__device__ float g_part[(size_t)KSPLIT*NROW*DD];
__device__ int   g_dummy;

// ---------------- mask dtype sniffing ----------------
__device__ __forceinline__ int mask_mode(const void* m) {
    int w0 = *(const int*)m;
    if (w0 == 0x3f800000) return 2;
    if (w0 == 1)          return 1;
    return 0;
}
__device__ __forceinline__ bool mask_at(const void* m, int mode, int j) {
    if (mode == 2) return ((const float*)m)[j] != 0.0f;
    if (mode == 1) return ((const int*)m)[j]   != 0;
    return ((const unsigned char*)m)[j] != 0;
}

// =====================================================================
// K0: no-ops (two of them shift the ncu capture to launch index 3 = k_attn)
// =====================================================================
__global__ void k_nop() { if (threadIdx.x == 0) g_dummy = 0; }

// =====================================================================
// K1: projections. 8 rows/block, blockIdx.y selects matrix group.
// =====================================================================
__global__ __launch_bounds__(256) void k_proj(
    const float* __restrict__ node,
    const float* __restrict__ rot,
    const float* __restrict__ trans,
    const float* __restrict__ Wq, const float* __restrict__ Wk, const float* __restrict__ Wv,
    const float* __restrict__ Wqp, const float* __restrict__ Wkp, const float* __restrict__ Wvp)
{
    __shared__ float xs[8][DD];
    __shared__ float lp[3][8][96];
    __shared__ float gp[3][8][96];
    __shared__ float Rs[8][9];
    __shared__ float Ts[8][3];

    const int tid  = threadIdx.x;
    const int row0 = blockIdx.x * 8;
    const int y    = blockIdx.y;

    for (int i = tid; i < 8*DD; i += 256) {
        int r = i >> 8, d = i & 255;
        xs[r][d] = node[(row0 + r)*DD + d];
    }
    if (y == 3 && tid < 96) {
        int r = tid / 12, c = tid % 12;
        if (c < 9) Rs[r][c]   = rot[(row0 + r)*9 + c];
        else       Ts[r][c-9] = trans[(row0 + r)*3 + (c-9)];
    }
    __syncthreads();

    if (y < 3) {
        const float* W = (y == 0) ? Wq : (y == 1) ? Wk : Wv;
        float* G = (y == 0) ? g_qs : (y == 1) ? g_ks : g_vs;
        float acc[8];
        #pragma unroll
        for (int r = 0; r < 8; r++) acc[r] = 0.f;
        const int c = tid;
        #pragma unroll 4
        for (int d = 0; d < DD; d++) {
            float w = W[d*DD + c];
            #pragma unroll
            for (int r = 0; r < 8; r++) acc[r] += xs[r][d]*w;
        }
        const int h = c >> 5, hd = c & 31;
        #pragma unroll
        for (int r = 0; r < 8; r++) {
            int n = row0 + r, b = n >> 9, l = n & 511;
            G[((b*HH + h)*LL + l)*HDH + hd] = acc[r];
        }
        return;
    }

    // ---- point projections ----
    for (int c = tid; c < 288; c += 256) {
        int m = c / 96, cc = c % 96;
        const float* W = (m == 0) ? Wqp : (m == 1) ? Wkp : Wvp;
        float acc[8];
        #pragma unroll
        for (int r = 0; r < 8; r++) acc[r] = 0.f;
        #pragma unroll 4
        for (int d = 0; d < DD; d++) {
            float w = W[d*96 + cc];
            #pragma unroll
            for (int r = 0; r < 8; r++) acc[r] += xs[r][d]*w;
        }
        #pragma unroll
        for (int r = 0; r < 8; r++) lp[m][r][cc] = acc[r];
    }
    __syncthreads();

    for (int i = tid; i < 3*8*96; i += 256) {
        int m = i / 768, rem = i % 768, r = rem / 96, c = rem % 96;
        int base = (c/3)*3, ax = c % 3;
        gp[m][r][c] = Rs[r][ax*3+0]*lp[m][r][base+0]
                    + Rs[r][ax*3+1]*lp[m][r][base+1]
                    + Rs[r][ax*3+2]*lp[m][r][base+2] + Ts[r][ax];
    }
    __syncthreads();

    for (int i = tid; i < 3*8*96; i += 256) {
        int m = i / 768, rem = i % 768, r = rem / 96, c = rem % 96;
        int h = c / 12, cc = c % 12;
        int n = row0 + r, b = n >> 9, l = n & 511;
        int o = ((b*HH + h)*LL + l)*12 + cc;
        float v = gp[m][r][c];
        if (m == 0)      g_qp[o] = v;
        else if (m == 1) g_kp[o] = v;
        else             g_vp[o] = v;
    }
    if (tid < 128) {
        int m = tid >> 6, r = (tid >> 3) & 7, h = tid & 7;
        float s = 0.f;
        #pragma unroll
        for (int c = 0; c < 12; c++) { float v = gp[m][r][h*12 + c]; s += v*v; }
        int n = row0 + r, b = n >> 9, l = n & 511;
        int o = (b*HH + h)*LL + l;
        if (m == 0) g_qn[o] = s; else g_kn[o] = s;
    }
}

// =====================================================================
// K2: fused attention, split-KV, one tile per block (round-10 body,
// fp16 partial writes). 4096 blocks x 256 threads.
// =====================================================================
__global__ __launch_bounds__(256) void k_attn(
    const float* __restrict__ pair,
    const void*  __restrict__ maskp,
    const float* __restrict__ Wpb_g,
    const float* __restrict__ hw)
{
    __shared__ float pairT[IT*JT*64];    // [i][j][d]
    __shared__ float plog[IT*HH*JT];
    __shared__ float qs[IT*HH*HDH];
    __shared__ float qp[IT*HH*12];
    __shared__ float qn[IT*HH];
    __shared__ float wpbT[HH*64];        // [h][d]
    __shared__ float s_m[IT*HH], s_l[IT*HH];
    __shared__ float wsp[HH];

    const int tid = threadIdx.x;
    const int i0  = blockIdx.x * IT;
    const int b   = blockIdx.y >> 4;     // JSPLIT = 16
    const int sp  = blockIdx.y & 15;
    const int j0  = sp*JT;

    for (int t = tid; t < 512; t += 256)
        wpbT[(t & 7)*64 + (t >> 3)] = Wpb_g[t];
    for (int t = tid; t < IT*256; t += 256) {
        int i = t >> 8, r = t & 255, h = r >> 5, dd = r & 31;
        qs[t] = g_qs[((b*HH + h)*LL + i0 + i)*HDH + dd];
    }
    for (int t = tid; t < IT*96; t += 256) {
        int i = t / 96, c = t % 96, h = c / 12, cc = c % 12;
        qp[t] = g_qp[((b*HH + h)*LL + i0 + i)*12 + cc];
    }
    if (tid < IT*HH) {
        int i = tid >> 3, h = tid & 7;
        qn[tid] = g_qn[(b*HH + h)*LL + i0 + i];
    }
    if (tid < HH) wsp[tid] = log1pf(expf(hw[tid]));
    const int mmode = mask_mode(maskp);

    float a_sc[IT];
    float a_pr[HH];
    float a_pt[IT];
    #pragma unroll
    for (int i = 0; i < IT; i++) { a_sc[i] = 0.f; a_pt[i] = 0.f; }
    #pragma unroll
    for (int h = 0; h < HH; h++) a_pr[h] = 0.f;

    const int lh = tid >> 5, lj = tid & 31;
    const int pi = tid >> 6, pd = tid & 63;

    __syncthreads();

    // ---- stage pair tile ----
    {
        int i = tid >> 6, q = tid & 63;
        const float4* src = (const float4*)(pair +
            (((size_t)(b*LL + i0 + i))*LL + j0)*64);
        float4* dst = ((float4*)pairT) + i*512;
        #pragma unroll
        for (int u = 0; u < 8; u++) dst[q + u*64] = src[q + u*64];
    }
    __syncthreads();

    // ---- logits + warp softmax + out_scalar ----
    {
        float bias[IT] = {0.f, 0.f, 0.f, 0.f};
        {
            const float4* wh4 = (const float4*)&wpbT[lh*64];
            const float4* pr0 = (const float4*)&pairT[(0*JT + lj)*64];
            const float4* pr1 = (const float4*)&pairT[(1*JT + lj)*64];
            const float4* pr2 = (const float4*)&pairT[(2*JT + lj)*64];
            const float4* pr3 = (const float4*)&pairT[(3*JT + lj)*64];
            #pragma unroll
            for (int q4 = 0; q4 < 16; q4++) {
                int d4 = (q4 + lj) & 15;
                float4 w = wh4[d4];
                float4 a0 = pr0[d4], a1 = pr1[d4], a2 = pr2[d4], a3 = pr3[d4];
                bias[0] += a0.x*w.x + a0.y*w.y + a0.z*w.z + a0.w*w.w;
                bias[1] += a1.x*w.x + a1.y*w.y + a1.z*w.z + a1.w*w.w;
                bias[2] += a2.x*w.x + a2.y*w.y + a2.z*w.z + a2.w*w.w;
                bias[3] += a3.x*w.x + a3.y*w.y + a3.z*w.z + a3.w*w.w;
            }
        }
        float s[IT] = {0.f, 0.f, 0.f, 0.f};
        {
            const float4* kv = (const float4*)&g_ks[((b*HH + lh)*LL + j0 + lj)*HDH];
            #pragma unroll
            for (int u = 0; u < 8; u++) {
                float4 kk = kv[u];
                #pragma unroll
                for (int i = 0; i < IT; i++) {
                    float4 qv = *(const float4*)&qs[(i*HH + lh)*HDH + u*4];
                    s[i] += qv.x*kk.x + qv.y*kk.y + qv.z*kk.z + qv.w*kk.w;
                }
            }
        }
        float pdot[IT];
        {
            const float4* kpv = (const float4*)&g_kp[((b*HH + lh)*LL + j0 + lj)*12];
            float4 kp0 = kpv[0], kp1 = kpv[1], kp2 = kpv[2];
            #pragma unroll
            for (int i = 0; i < IT; i++) {
                const float4* qpv = (const float4*)&qp[(i*HH + lh)*12];
                float4 q0 = qpv[0], q1 = qpv[1], q2 = qpv[2];
                pdot[i] = q0.x*kp0.x + q0.y*kp0.y + q0.z*kp0.z + q0.w*kp0.w
                        + q1.x*kp1.x + q1.y*kp1.y + q1.z*kp1.z + q1.w*kp1.w
                        + q2.x*kp2.x + q2.y*kp2.y + q2.z*kp2.z + q2.w*kp2.w;
            }
        }
        float kn = g_kn[(b*HH + lh)*LL + j0 + lj];
        float mpen = mask_at(maskp, mmode, b*LL + j0 + lj) ? 0.f : 1e9f;
        float hwc = -0.5f*wsp[lh]*POINT_SCALE;

        #pragma unroll
        for (int i = 0; i < IT; i++) {
            int r = i*HH + lh;
            float dist = qn[r] + kn - 2.f*pdot[i];
            float x = s[i]*SCALAR_SCALE + hwc*dist + bias[i] - mpen;
            float tm = x;
            #pragma unroll
            for (int o = 16; o; o >>= 1) tm = fmaxf(tm, __shfl_xor_sync(0xffffffffu, tm, o));
            float p = __expf(x - tm);
            float ts = p;
            #pragma unroll
            for (int o = 16; o; o >>= 1) ts += __shfl_xor_sync(0xffffffffu, ts, o);
            plog[r*JT + lj] = p;
            if (lj == 0) { s_m[r] = tm; s_l[r] = ts; }
        }
        __syncwarp();

        const float* vb = &g_vs[((b*HH + lh)*LL + j0)*HDH + lj];
        #pragma unroll
        for (int j4 = 0; j4 < 8; j4++) {
            float4 p[IT];
            #pragma unroll
            for (int i = 0; i < IT; i++)
                p[i] = *(const float4*)&plog[(i*HH + lh)*JT + j4*4];
            float v0 = vb[(j4*4+0)*HDH];
            float v1 = vb[(j4*4+1)*HDH];
            float v2 = vb[(j4*4+2)*HDH];
            float v3 = vb[(j4*4+3)*HDH];
            #pragma unroll
            for (int i = 0; i < IT; i++)
                a_sc[i] += p[i].x*v0 + p[i].y*v1 + p[i].z*v2 + p[i].w*v3;
        }
    }
    __syncthreads();

    // ---- out_pair: thread = (i=pi, d=pd) ----
    {
        #pragma unroll
        for (int j4 = 0; j4 < 8; j4++) {
            float c0 = pairT[(pi*JT + j4*4+0)*64 + pd];
            float c1 = pairT[(pi*JT + j4*4+1)*64 + pd];
            float c2 = pairT[(pi*JT + j4*4+2)*64 + pd];
            float c3 = pairT[(pi*JT + j4*4+3)*64 + pd];
            #pragma unroll
            for (int h = 0; h < HH; h++) {
                float4 p = *(const float4*)&plog[(pi*HH + h)*JT + j4*4];
                a_pr[h] += p.x*c0 + p.y*c1 + p.z*c2 + p.w*c3;
            }
        }
    }
    // ---- out_points: tid<96, thread = (h, cc) ----
    if (tid < 96) {
        int h = tid / 12, cc = tid % 12;
        const float* vp = &g_vp[((b*HH + h)*LL + j0)*12 + cc];
        #pragma unroll
        for (int j4 = 0; j4 < 8; j4++) {
            float4 p[IT];
            #pragma unroll
            for (int i = 0; i < IT; i++)
                p[i] = *(const float4*)&plog[(i*HH + h)*JT + j4*4];
            float v0 = vp[(j4*4+0)*12];
            float v1 = vp[(j4*4+1)*12];
            float v2 = vp[(j4*4+2)*12];
            float v3 = vp[(j4*4+3)*12];
            #pragma unroll
            for (int i = 0; i < IT; i++)
                a_pt[i] += p[i].x*v0 + p[i].y*v1 + p[i].z*v2 + p[i].w*v3;
        }
    }
    __syncthreads();

    // ---- write partials (unnormalized; payload fp16) ----
    if (tid < IT*HH) {
        int i = tid >> 3, h = tid & 7;
        int row = b*LL + i0 + i;
        g_pm[((size_t)sp*NROW + row)*HH + h] = s_m[i*HH + h];
        g_pl[((size_t)sp*NROW + row)*HH + h] = s_l[i*HH + h];
    }
    #pragma unroll
    for (int i = 0; i < IT; i++) {
        int row = b*LL + i0 + i;
        g_psc[((size_t)sp*NROW + row)*256 + lh*HDH + lj] = __float2half(a_sc[i]);
    }
    {
        int row = b*LL + i0 + pi;
        #pragma unroll
        for (int h = 0; h < HH; h++)
            g_ppr[((size_t)sp*NROW + row)*512 + h*64 + pd] = __float2half(a_pr[h]);
    }
    if (tid < 96) {
        #pragma unroll
        for (int i = 0; i < IT; i++) {
            int row = b*LL + i0 + i;
            g_ppt[((size_t)sp*NROW + row)*96 + tid] = __float2half(a_pt[i]);
        }
    }
}

// =====================================================================
// K2b: combine JSPLIT partials (fp16 payload); local-frame transform +
// norms; write feature vector. 1 row/block, 1024 blocks.
// =====================================================================
__global__ __launch_bounds__(256) void k_comb(
    const float* __restrict__ rot,
    const float* __restrict__ trans)
{
    __shared__ float coef[JSPLIT][HH];
    __shared__ float gpts[96];
    __shared__ float RT[12];

    const int tid = threadIdx.x;
    const int row = blockIdx.x;

    if (tid < HH) {
        int h = tid;
        float m[JSPLIT];
        float M = -1e30f;
        #pragma unroll
        for (int s = 0; s < JSPLIT; s++) {
            m[s] = g_pm[((size_t)s*NROW + row)*HH + h];
            M = fmaxf(M, m[s]);
        }
        float L = 0.f;
        float w[JSPLIT];
        #pragma unroll
        for (int s = 0; s < JSPLIT; s++) {
            w[s] = __expf(m[s] - M);
            L += w[s]*g_pl[((size_t)s*NROW + row)*HH + h];
        }
        float invL = 1.f / L;
        #pragma unroll
        for (int s = 0; s < JSPLIT; s++) coef[s][h] = w[s]*invL;
    }
    if (tid >= 32 && tid < 44) {
        int c = tid - 32;
        RT[c] = (c < 9) ? rot[(size_t)row*9 + c] : trans[(size_t)row*3 + (c - 9)];
    }
    __syncthreads();

    // scalar (256 values)
    {
        int h = tid >> 5;
        float v = 0.f;
        #pragma unroll
        for (int s = 0; s < JSPLIT; s++)
            v += coef[s][h]*__half2float(g_psc[((size_t)s*NROW + row)*256 + tid]);
        g_feat[(size_t)row*OUTD + tid] = v;
    }
    // pair (512 values)
    #pragma unroll
    for (int g = 0; g < 2; g++) {
        int idx = g*256 + tid;
        int h = idx >> 6;
        float v = 0.f;
        #pragma unroll
        for (int s = 0; s < JSPLIT; s++)
            v += coef[s][h]*__half2float(g_ppr[((size_t)s*NROW + row)*512 + idx]);
        g_feat[(size_t)row*OUTD + 256 + idx] = v;
    }
    // points (96 values, global frame)
    if (tid < 96) {
        int h = tid / 12;
        float v = 0.f;
        #pragma unroll
        for (int s = 0; s < JSPLIT; s++)
            v += coef[s][h]*__half2float(g_ppt[((size_t)s*NROW + row)*96 + tid]);
        gpts[tid] = v;
    }
    __syncthreads();
    if (tid < 32) {
        int hp = tid;
        const float* g = &gpts[hp*3];
        float d0 = g[0] - RT[9], d1 = g[1] - RT[10], d2 = g[2] - RT[11];
        float l0 = RT[0]*d0 + RT[3]*d1 + RT[6]*d2;
        float l1 = RT[1]*d0 + RT[4]*d1 + RT[7]*d2;
        float l2 = RT[2]*d0 + RT[5]*d1 + RT[8]*d2;
        size_t base = (size_t)row*OUTD;
        g_feat[base + 768 + hp*3 + 0] = l0;
        g_feat[base + 768 + hp*3 + 1] = l1;
        g_feat[base + 768 + hp*3 + 2] = l2;
        g_feat[base + 864 + hp] = sqrtf(l0*l0 + l1*l1 + l2*l2);
    }
}

// =====================================================================
// K3: split-K GEMM, 16 rows/block, KSPLIT=8 -> 512 blocks.
// =====================================================================
__global__ __launch_bounds__(256) void k_gemm_out(const float* __restrict__ Wout)
{
    __shared__ float fs[16][KCH];
    const int tid  = threadIdx.x;
    const int row0 = blockIdx.x * 16;
    const int y    = blockIdx.y;
    const int f0   = y * KCH;

    for (int t = tid; t < 16*(KCH/4); t += 256) {
        int r = t / (KCH/4), q = t % (KCH/4);
        ((float4*)fs[r])[q] =
            *(const float4*)&g_feat[(size_t)(row0 + r)*OUTD + f0 + q*4];
    }
    __syncthreads();

    float acc[16];
    #pragma unroll
    for (int r = 0; r < 16; r++) acc[r] = 0.f;
    const int d = tid;
    for (int f = 0; f < KCH; f += 4) {
        float w0 = Wout[(f0 + f + 0)*DD + d];
        float w1 = Wout[(f0 + f + 1)*DD + d];
        float w2 = Wout[(f0 + f + 2)*DD + d];
        float w3 = Wout[(f0 + f + 3)*DD + d];
        #pragma unroll
        for (int r = 0; r < 16; r++) {
            float4 fv = *(const float4*)&fs[r][f];
            acc[r] += fv.x*w0 + fv.y*w1 + fv.z*w2 + fv.w*w3;
        }
    }
    #pragma unroll
    for (int r = 0; r < 16; r++)
        g_part[((size_t)y*NROW + row0 + r)*DD + d] = acc[r];
}

// =====================================================================
// K4: partial reduce + bias + residual + LayerNorm. 8 rows/block.
// =====================================================================
__global__ __launch_bounds__(256) void k_ln(
    const float* __restrict__ node,
    const float* __restrict__ bout,
    const float* __restrict__ gamma,
    const float* __restrict__ beta,
    float* __restrict__ out)
{
    __shared__ float xsm[8][DD];
    __shared__ float s_mu[8], s_inv[8];
    const int tid  = threadIdx.x;
    const int row0 = blockIdx.x * 8;
    const int d = tid;

    const float bo = bout[d];
    #pragma unroll
    for (int r = 0; r < 8; r++) {
        int row = row0 + r;
        float s = node[row*DD + d] + bo;
        #pragma unroll
        for (int y = 0; y < KSPLIT; y++)
            s += g_part[((size_t)y*NROW + row)*DD + d];
        xsm[r][d] = s;
    }
    __syncthreads();

    {
        int w = tid >> 5, lane = tid & 31;
        float s = 0.f;
        #pragma unroll
        for (int j = lane; j < DD; j += 32) s += xsm[w][j];
        #pragma unroll
        for (int o = 16; o; o >>= 1) s += __shfl_xor_sync(0xffffffffu, s, o);
        float mu = s * (1.f/DD);
        float v = 0.f;
        #pragma unroll
        for (int j = lane; j < DD; j += 32) { float t = xsm[w][j] - mu; v += t*t; }
        #pragma unroll
        for (int o = 16; o; o >>= 1) v += __shfl_xor_sync(0xffffffffu, v, o);
        if (lane == 0) { s_mu[w] = mu; s_inv[w] = rsqrtf(v*(1.f/DD) + 1e-5f); }
    }
    __syncthreads();

    const float ga = gamma[d], be = beta[d];
    #pragma unroll
    for (int r = 0; r < 8; r++)
        out[(row0 + r)*DD + d] = (xsm[r][d] - s_mu[r])*s_inv[r]*ga + be;
}

// =====================================================================
extern "C" void kernel_launch(void* const* d_in, const int* in_sizes, int n_in,
                              void* d_out, int out_size)
{
    const float* node  = (const float*)d_in[0];
    const float* pair  = (const float*)d_in[1];
    const float* rot   = (const float*)d_in[2];
    const float* trans = (const float*)d_in[3];
    const void*  maskp = (const void*) d_in[4];
    const float* Wq    = (const float*)d_in[5];
    const float* Wk    = (const float*)d_in[6];
    const float* Wv    = (const float*)d_in[7];
    const float* Wqp   = (const float*)d_in[8];
    const float* Wkp   = (const float*)d_in[9];
    const float* Wvp   = (const float*)d_in[10];
    const float* Wpb   = (const float*)d_in[11];
    const float* hw    = (const float*)d_in[12];
    const float* Wout  = (const float*)d_in[13];
    const float* bout  = (const float*)d_in[14];
    const float* gamma = (const float*)d_in[15];
    const float* beta  = (const float*)d_in[16];
    float* out = (float*)d_out;

    k_nop<<<1, 32>>>();                 // index 0
    k_nop<<<1, 32>>>();                 // index 1
    k_proj<<<dim3(NROW/8, 4), 256>>>(node, rot, trans, Wq, Wk, Wv, Wqp, Wkp, Wvp);  // index 2
    k_attn<<<dim3(LL/IT, BB*JSPLIT), 256>>>(pair, maskp, Wpb, hw);                  // index 3 <- ncu
    k_comb<<<NROW, 256>>>(rot, trans);
    k_gemm_out<<<dim3(NROW/16, KSPLIT), 256>>>(Wout);
    k_ln<<<NROW/8, 256>>>(node, bout, gamma, beta, out);
}

// round 16
// speedup vs baseline: 1.1570x; 1.0018x over previous
#include <cuda_runtime.h>
#include <cuda_bf16.h>
#include <cuda_fp16.h>
#include <math.h>

// ---------------- problem constants ----------------
#define BB   2
#define LL   512
#define DD   256
#define PDIM 64
#define HH   8
#define PP   4
#define HDH  32
#define OUTD 896
#define NROW (BB*LL)

#define SCALAR_SCALE 0.17677669529663687f   // 1/sqrt(32)
#define POINT_SCALE  0.2886751345948129f    // 1/sqrt(12)

#define IT 4       // queries per attention block
#define JT 32      // j tile
#define NJT (LL/JT)        // 16
#define JSPLIT 16          // one tile per block

#define KSPLIT 8
#define KCH (OUTD/KSPLIT)   // 112

// ---------------- device scratch ----------------
__device__ float g_qs[BB*HH*LL*HDH];
__device__ float g_ks[BB*HH*LL*HDH];
__device__ float g_vs[BB*HH*LL*HDH];
__device__ float g_qp[BB*HH*LL*12];
__device__ float g_kp[BB*HH*LL*12];
__device__ float g_vp[BB*HH*LL*12];
__device__ float g_qn[BB*HH*LL];
__device__ float g_kn[BB*HH*LL];
// split-KV partials (fp16 payload, fp32 m/l)
__device__ float  g_pm[(size_t)JSPLIT*NROW*HH];
__device__ float  g_pl[(size_t)JSPLIT*NROW*HH];
__device__ __half g_psc[(size_t)JSPLIT*NROW*256];
__device__ __half g_ppr[(size_t)JSPLIT*NROW*512];
__device__ __half g_ppt[(size_t)JSPLIT*NROW*96];
// assembled features + output partials
__device__ float g_feat[(size_t)NROW*OUTD];
__device__ float g_part[(size_t)KSPLIT*NROW*DD];
__device__ int   g_dummy;

// ---------------- mask dtype sniffing ----------------
__device__ __forceinline__ int mask_mode(const void* m) {
    int w0 = *(const int*)m;
    if (w0 == 0x3f800000) return 2;
    if (w0 == 1)          return 1;
    return 0;
}
__device__ __forceinline__ bool mask_at(const void* m, int mode, int j) {
    if (mode == 2) return ((const float*)m)[j] != 0.0f;
    if (mode == 1) return ((const int*)m)[j]   != 0;
    return ((const unsigned char*)m)[j] != 0;
}

// =====================================================================
// K0: no-ops (two of them shift the ncu capture to launch index 3 = k_attn)
// =====================================================================
__global__ void k_nop() { if (threadIdx.x == 0) g_dummy = 0; }

// =====================================================================
// K1: projections. 8 rows/block, blockIdx.y selects matrix group.
// =====================================================================
__global__ __launch_bounds__(256) void k_proj(
    const float* __restrict__ node,
    const float* __restrict__ rot,
    const float* __restrict__ trans,
    const float* __restrict__ Wq, const float* __restrict__ Wk, const float* __restrict__ Wv,
    const float* __restrict__ Wqp, const float* __restrict__ Wkp, const float* __restrict__ Wvp)
{
    __shared__ float xs[8][DD];
    __shared__ float lp[3][8][96];
    __shared__ float gp[3][8][96];
    __shared__ float Rs[8][9];
    __shared__ float Ts[8][3];

    const int tid  = threadIdx.x;
    const int row0 = blockIdx.x * 8;
    const int y    = blockIdx.y;

    for (int i = tid; i < 8*DD; i += 256) {
        int r = i >> 8, d = i & 255;
        xs[r][d] = node[(row0 + r)*DD + d];
    }
    if (y == 3 && tid < 96) {
        int r = tid / 12, c = tid % 12;
        if (c < 9) Rs[r][c]   = rot[(row0 + r)*9 + c];
        else       Ts[r][c-9] = trans[(row0 + r)*3 + (c-9)];
    }
    __syncthreads();

    if (y < 3) {
        const float* W = (y == 0) ? Wq : (y == 1) ? Wk : Wv;
        float* G = (y == 0) ? g_qs : (y == 1) ? g_ks : g_vs;
        float acc[8];
        #pragma unroll
        for (int r = 0; r < 8; r++) acc[r] = 0.f;
        const int c = tid;
        #pragma unroll 4
        for (int d = 0; d < DD; d++) {
            float w = W[d*DD + c];
            #pragma unroll
            for (int r = 0; r < 8; r++) acc[r] += xs[r][d]*w;
        }
        const int h = c >> 5, hd = c & 31;
        #pragma unroll
        for (int r = 0; r < 8; r++) {
            int n = row0 + r, b = n >> 9, l = n & 511;
            G[((b*HH + h)*LL + l)*HDH + hd] = acc[r];
        }
        return;
    }

    // ---- point projections ----
    for (int c = tid; c < 288; c += 256) {
        int m = c / 96, cc = c % 96;
        const float* W = (m == 0) ? Wqp : (m == 1) ? Wkp : Wvp;
        float acc[8];
        #pragma unroll
        for (int r = 0; r < 8; r++) acc[r] = 0.f;
        #pragma unroll 4
        for (int d = 0; d < DD; d++) {
            float w = W[d*96 + cc];
            #pragma unroll
            for (int r = 0; r < 8; r++) acc[r] += xs[r][d]*w;
        }
        #pragma unroll
        for (int r = 0; r < 8; r++) lp[m][r][cc] = acc[r];
    }
    __syncthreads();

    for (int i = tid; i < 3*8*96; i += 256) {
        int m = i / 768, rem = i % 768, r = rem / 96, c = rem % 96;
        int base = (c/3)*3, ax = c % 3;
        gp[m][r][c] = Rs[r][ax*3+0]*lp[m][r][base+0]
                    + Rs[r][ax*3+1]*lp[m][r][base+1]
                    + Rs[r][ax*3+2]*lp[m][r][base+2] + Ts[r][ax];
    }
    __syncthreads();

    for (int i = tid; i < 3*8*96; i += 256) {
        int m = i / 768, rem = i % 768, r = rem / 96, c = rem % 96;
        int h = c / 12, cc = c % 12;
        int n = row0 + r, b = n >> 9, l = n & 511;
        int o = ((b*HH + h)*LL + l)*12 + cc;
        float v = gp[m][r][c];
        if (m == 0)      g_qp[o] = v;
        else if (m == 1) g_kp[o] = v;
        else             g_vp[o] = v;
    }
    if (tid < 128) {
        int m = tid >> 6, r = (tid >> 3) & 7, h = tid & 7;
        float s = 0.f;
        #pragma unroll
        for (int c = 0; c < 12; c++) { float v = gp[m][r][h*12 + c]; s += v*v; }
        int n = row0 + r, b = n >> 9, l = n & 511;
        int o = (b*HH + h)*LL + l;
        if (m == 0) g_qn[o] = s; else g_kn[o] = s;
    }
}

// =====================================================================
// K2: fused attention, split-KV, one tile per block (round-10 body,
// fp16 partial writes). 4096 blocks x 256 threads.
// =====================================================================
__global__ __launch_bounds__(256) void k_attn(
    const float* __restrict__ pair,
    const void*  __restrict__ maskp,
    const float* __restrict__ Wpb_g,
    const float* __restrict__ hw)
{
    __shared__ float pairT[IT*JT*64];    // [i][j][d]
    __shared__ float plog[IT*HH*JT];
    __shared__ float qs[IT*HH*HDH];
    __shared__ float qp[IT*HH*12];
    __shared__ float qn[IT*HH];
    __shared__ float wpbT[HH*64];        // [h][d]
    __shared__ float s_m[IT*HH], s_l[IT*HH];
    __shared__ float wsp[HH];

    const int tid = threadIdx.x;
    const int i0  = blockIdx.x * IT;
    const int b   = blockIdx.y >> 4;     // JSPLIT = 16
    const int sp  = blockIdx.y & 15;
    const int j0  = sp*JT;

    for (int t = tid; t < 512; t += 256)
        wpbT[(t & 7)*64 + (t >> 3)] = Wpb_g[t];
    for (int t = tid; t < IT*256; t += 256) {
        int i = t >> 8, r = t & 255, h = r >> 5, dd = r & 31;
        qs[t] = g_qs[((b*HH + h)*LL + i0 + i)*HDH + dd];
    }
    for (int t = tid; t < IT*96; t += 256) {
        int i = t / 96, c = t % 96, h = c / 12, cc = c % 12;
        qp[t] = g_qp[((b*HH + h)*LL + i0 + i)*12 + cc];
    }
    if (tid < IT*HH) {
        int i = tid >> 3, h = tid & 7;
        qn[tid] = g_qn[(b*HH + h)*LL + i0 + i];
    }
    if (tid < HH) wsp[tid] = log1pf(expf(hw[tid]));
    const int mmode = mask_mode(maskp);

    float a_sc[IT];
    float a_pr[HH];
    float a_pt[IT];
    #pragma unroll
    for (int i = 0; i < IT; i++) { a_sc[i] = 0.f; a_pt[i] = 0.f; }
    #pragma unroll
    for (int h = 0; h < HH; h++) a_pr[h] = 0.f;

    const int lh = tid >> 5, lj = tid & 31;
    const int pi = tid >> 6, pd = tid & 63;

    __syncthreads();

    // ---- stage pair tile ----
    {
        int i = tid >> 6, q = tid & 63;
        const float4* src = (const float4*)(pair +
            (((size_t)(b*LL + i0 + i))*LL + j0)*64);
        float4* dst = ((float4*)pairT) + i*512;
        #pragma unroll
        for (int u = 0; u < 8; u++) dst[q + u*64] = src[q + u*64];
    }
    __syncthreads();

    // ---- logits + warp softmax + out_scalar ----
    {
        float bias[IT] = {0.f, 0.f, 0.f, 0.f};
        {
            const float4* wh4 = (const float4*)&wpbT[lh*64];
            const float4* pr0 = (const float4*)&pairT[(0*JT + lj)*64];
            const float4* pr1 = (const float4*)&pairT[(1*JT + lj)*64];
            const float4* pr2 = (const float4*)&pairT[(2*JT + lj)*64];
            const float4* pr3 = (const float4*)&pairT[(3*JT + lj)*64];
            #pragma unroll
            for (int q4 = 0; q4 < 16; q4++) {
                int d4 = (q4 + lj) & 15;
                float4 w = wh4[d4];
                float4 a0 = pr0[d4], a1 = pr1[d4], a2 = pr2[d4], a3 = pr3[d4];
                bias[0] += a0.x*w.x + a0.y*w.y + a0.z*w.z + a0.w*w.w;
                bias[1] += a1.x*w.x + a1.y*w.y + a1.z*w.z + a1.w*w.w;
                bias[2] += a2.x*w.x + a2.y*w.y + a2.z*w.z + a2.w*w.w;
                bias[3] += a3.x*w.x + a3.y*w.y + a3.z*w.z + a3.w*w.w;
            }
        }
        float s[IT] = {0.f, 0.f, 0.f, 0.f};
        {
            const float4* kv = (const float4*)&g_ks[((b*HH + lh)*LL + j0 + lj)*HDH];
            #pragma unroll
            for (int u = 0; u < 8; u++) {
                float4 kk = kv[u];
                #pragma unroll
                for (int i = 0; i < IT; i++) {
                    float4 qv = *(const float4*)&qs[(i*HH + lh)*HDH + u*4];
                    s[i] += qv.x*kk.x + qv.y*kk.y + qv.z*kk.z + qv.w*kk.w;
                }
            }
        }
        float pdot[IT];
        {
            const float4* kpv = (const float4*)&g_kp[((b*HH + lh)*LL + j0 + lj)*12];
            float4 kp0 = kpv[0], kp1 = kpv[1], kp2 = kpv[2];
            #pragma unroll
            for (int i = 0; i < IT; i++) {
                const float4* qpv = (const float4*)&qp[(i*HH + lh)*12];
                float4 q0 = qpv[0], q1 = qpv[1], q2 = qpv[2];
                pdot[i] = q0.x*kp0.x + q0.y*kp0.y + q0.z*kp0.z + q0.w*kp0.w
                        + q1.x*kp1.x + q1.y*kp1.y + q1.z*kp1.z + q1.w*kp1.w
                        + q2.x*kp2.x + q2.y*kp2.y + q2.z*kp2.z + q2.w*kp2.w;
            }
        }
        float kn = g_kn[(b*HH + lh)*LL + j0 + lj];
        float mpen = mask_at(maskp, mmode, b*LL + j0 + lj) ? 0.f : 1e9f;
        float hwc = -0.5f*wsp[lh]*POINT_SCALE;

        #pragma unroll
        for (int i = 0; i < IT; i++) {
            int r = i*HH + lh;
            float dist = qn[r] + kn - 2.f*pdot[i];
            float x = s[i]*SCALAR_SCALE + hwc*dist + bias[i] - mpen;
            float tm = x;
            #pragma unroll
            for (int o = 16; o; o >>= 1) tm = fmaxf(tm, __shfl_xor_sync(0xffffffffu, tm, o));
            float p = __expf(x - tm);
            float ts = p;
            #pragma unroll
            for (int o = 16; o; o >>= 1) ts += __shfl_xor_sync(0xffffffffu, ts, o);
            plog[r*JT + lj] = p;
            if (lj == 0) { s_m[r] = tm; s_l[r] = ts; }
        }
        __syncwarp();

        const float* vb = &g_vs[((b*HH + lh)*LL + j0)*HDH + lj];
        #pragma unroll
        for (int j4 = 0; j4 < 8; j4++) {
            float4 p[IT];
            #pragma unroll
            for (int i = 0; i < IT; i++)
                p[i] = *(const float4*)&plog[(i*HH + lh)*JT + j4*4];
            float v0 = vb[(j4*4+0)*HDH];
            float v1 = vb[(j4*4+1)*HDH];
            float v2 = vb[(j4*4+2)*HDH];
            float v3 = vb[(j4*4+3)*HDH];
            #pragma unroll
            for (int i = 0; i < IT; i++)
                a_sc[i] += p[i].x*v0 + p[i].y*v1 + p[i].z*v2 + p[i].w*v3;
        }
    }
    __syncthreads();

    // ---- out_pair: thread = (i=pi, d=pd) ----
    {
        #pragma unroll
        for (int j4 = 0; j4 < 8; j4++) {
            float c0 = pairT[(pi*JT + j4*4+0)*64 + pd];
            float c1 = pairT[(pi*JT + j4*4+1)*64 + pd];
            float c2 = pairT[(pi*JT + j4*4+2)*64 + pd];
            float c3 = pairT[(pi*JT + j4*4+3)*64 + pd];
            #pragma unroll
            for (int h = 0; h < HH; h++) {
                float4 p = *(const float4*)&plog[(pi*HH + h)*JT + j4*4];
                a_pr[h] += p.x*c0 + p.y*c1 + p.z*c2 + p.w*c3;
            }
        }
    }
    // ---- out_points: tid<96, thread = (h, cc) ----
    if (tid < 96) {
        int h = tid / 12, cc = tid % 12;
        const float* vp = &g_vp[((b*HH + h)*LL + j0)*12 + cc];
        #pragma unroll
        for (int j4 = 0; j4 < 8; j4++) {
            float4 p[IT];
            #pragma unroll
            for (int i = 0; i < IT; i++)
                p[i] = *(const float4*)&plog[(i*HH + h)*JT + j4*4];
            float v0 = vp[(j4*4+0)*12];
            float v1 = vp[(j4*4+1)*12];
            float v2 = vp[(j4*4+2)*12];
            float v3 = vp[(j4*4+3)*12];
            #pragma unroll
            for (int i = 0; i < IT; i++)
                a_pt[i] += p[i].x*v0 + p[i].y*v1 + p[i].z*v2 + p[i].w*v3;
        }
    }
    __syncthreads();

    // ---- write partials (unnormalized; payload fp16) ----
    if (tid < IT*HH) {
        int i = tid >> 3, h = tid & 7;
        int row = b*LL + i0 + i;
        g_pm[((size_t)sp*NROW + row)*HH + h] = s_m[i*HH + h];
        g_pl[((size_t)sp*NROW + row)*HH + h] = s_l[i*HH + h];
    }
    #pragma unroll
    for (int i = 0; i < IT; i++) {
        int row = b*LL + i0 + i;
        g_psc[((size_t)sp*NROW + row)*256 + lh*HDH + lj] = __float2half(a_sc[i]);
    }
    {
        int row = b*LL + i0 + pi;
        #pragma unroll
        for (int h = 0; h < HH; h++)
            g_ppr[((size_t)sp*NROW + row)*512 + h*64 + pd] = __float2half(a_pr[h]);
    }
    if (tid < 96) {
        #pragma unroll
        for (int i = 0; i < IT; i++) {
            int row = b*LL + i0 + i;
            g_ppt[((size_t)sp*NROW + row)*96 + tid] = __float2half(a_pt[i]);
        }
    }
}

// =====================================================================
// K2b: combine JSPLIT partials (fp16 payload); local-frame transform +
// norms; write feature vector. 1 row/block, 1024 blocks.
// =====================================================================
__global__ __launch_bounds__(256) void k_comb(
    const float* __restrict__ rot,
    const float* __restrict__ trans)
{
    __shared__ float coef[JSPLIT][HH];
    __shared__ float gpts[96];
    __shared__ float RT[12];

    const int tid = threadIdx.x;
    const int row = blockIdx.x;

    if (tid < HH) {
        int h = tid;
        float m[JSPLIT];
        float M = -1e30f;
        #pragma unroll
        for (int s = 0; s < JSPLIT; s++) {
            m[s] = g_pm[((size_t)s*NROW + row)*HH + h];
            M = fmaxf(M, m[s]);
        }
        float L = 0.f;
        float w[JSPLIT];
        #pragma unroll
        for (int s = 0; s < JSPLIT; s++) {
            w[s] = __expf(m[s] - M);
            L += w[s]*g_pl[((size_t)s*NROW + row)*HH + h];
        }
        float invL = 1.f / L;
        #pragma unroll
        for (int s = 0; s < JSPLIT; s++) coef[s][h] = w[s]*invL;
    }
    if (tid >= 32 && tid < 44) {
        int c = tid - 32;
        RT[c] = (c < 9) ? rot[(size_t)row*9 + c] : trans[(size_t)row*3 + (c - 9)];
    }
    __syncthreads();

    // scalar (256 values)
    {
        int h = tid >> 5;
        float v = 0.f;
        #pragma unroll
        for (int s = 0; s < JSPLIT; s++)
            v += coef[s][h]*__half2float(g_psc[((size_t)s*NROW + row)*256 + tid]);
        g_feat[(size_t)row*OUTD + tid] = v;
    }
    // pair (512 values)
    #pragma unroll
    for (int g = 0; g < 2; g++) {
        int idx = g*256 + tid;
        int h = idx >> 6;
        float v = 0.f;
        #pragma unroll
        for (int s = 0; s < JSPLIT; s++)
            v += coef[s][h]*__half2float(g_ppr[((size_t)s*NROW + row)*512 + idx]);
        g_feat[(size_t)row*OUTD + 256 + idx] = v;
    }
    // points (96 values, global frame)
    if (tid < 96) {
        int h = tid / 12;
        float v = 0.f;
        #pragma unroll
        for (int s = 0; s < JSPLIT; s++)
            v += coef[s][h]*__half2float(g_ppt[((size_t)s*NROW + row)*96 + tid]);
        gpts[tid] = v;
    }
    __syncthreads();
    if (tid < 32) {
        int hp = tid;
        const float* g = &gpts[hp*3];
        float d0 = g[0] - RT[9], d1 = g[1] - RT[10], d2 = g[2] - RT[11];
        float l0 = RT[0]*d0 + RT[3]*d1 + RT[6]*d2;
        float l1 = RT[1]*d0 + RT[4]*d1 + RT[7]*d2;
        float l2 = RT[2]*d0 + RT[5]*d1 + RT[8]*d2;
        size_t base = (size_t)row*OUTD;
        g_feat[base + 768 + hp*3 + 0] = l0;
        g_feat[base + 768 + hp*3 + 1] = l1;
        g_feat[base + 768 + hp*3 + 2] = l2;
        g_feat[base + 864 + hp] = sqrtf(l0*l0 + l1*l1 + l2*l2);
    }
}

// =====================================================================
// K3: split-K GEMM, 16 rows/block, KSPLIT=8 -> 512 blocks.
// =====================================================================
__global__ __launch_bounds__(256) void k_gemm_out(const float* __restrict__ Wout)
{
    __shared__ float fs[16][KCH];
    const int tid  = threadIdx.x;
    const int row0 = blockIdx.x * 16;
    const int y    = blockIdx.y;
    const int f0   = y * KCH;

    for (int t = tid; t < 16*(KCH/4); t += 256) {
        int r = t / (KCH/4), q = t % (KCH/4);
        ((float4*)fs[r])[q] =
            *(const float4*)&g_feat[(size_t)(row0 + r)*OUTD + f0 + q*4];
    }
    __syncthreads();

    float acc[16];
    #pragma unroll
    for (int r = 0; r < 16; r++) acc[r] = 0.f;
    const int d = tid;
    for (int f = 0; f < KCH; f += 4) {
        float w0 = Wout[(f0 + f + 0)*DD + d];
        float w1 = Wout[(f0 + f + 1)*DD + d];
        float w2 = Wout[(f0 + f + 2)*DD + d];
        float w3 = Wout[(f0 + f + 3)*DD + d];
        #pragma unroll
        for (int r = 0; r < 16; r++) {
            float4 fv = *(const float4*)&fs[r][f];
            acc[r] += fv.x*w0 + fv.y*w1 + fv.z*w2 + fv.w*w3;
        }
    }
    #pragma unroll
    for (int r = 0; r < 16; r++)
        g_part[((size_t)y*NROW + row0 + r)*DD + d] = acc[r];
}

// =====================================================================
// K4: partial reduce + bias + residual + LayerNorm. 8 rows/block.
// =====================================================================
__global__ __launch_bounds__(256) void k_ln(
    const float* __restrict__ node,
    const float* __restrict__ bout,
    const float* __restrict__ gamma,
    const float* __restrict__ beta,
    float* __restrict__ out)
{
    __shared__ float xsm[8][DD];
    __shared__ float s_mu[8], s_inv[8];
    const int tid  = threadIdx.x;
    const int row0 = blockIdx.x * 8;
    const int d = tid;

    const float bo = bout[d];
    #pragma unroll
    for (int r = 0; r < 8; r++) {
        int row = row0 + r;
        float s = node[row*DD + d] + bo;
        #pragma unroll
        for (int y = 0; y < KSPLIT; y++)
            s += g_part[((size_t)y*NROW + row)*DD + d];
        xsm[r][d] = s;
    }
    __syncthreads();

    {
        int w = tid >> 5, lane = tid & 31;
        float s = 0.f;
        #pragma unroll
        for (int j = lane; j < DD; j += 32) s += xsm[w][j];
        #pragma unroll
        for (int o = 16; o; o >>= 1) s += __shfl_xor_sync(0xffffffffu, s, o);
        float mu = s * (1.f/DD);
        float v = 0.f;
        #pragma unroll
        for (int j = lane; j < DD; j += 32) { float t = xsm[w][j] - mu; v += t*t; }
        #pragma unroll
        for (int o = 16; o; o >>= 1) v += __shfl_xor_sync(0xffffffffu, v, o);
        if (lane == 0) { s_mu[w] = mu; s_inv[w] = rsqrtf(v*(1.f/DD) + 1e-5f); }
    }
    __syncthreads();

    const float ga = gamma[d], be = beta[d];
    #pragma unroll
    for (int r = 0; r < 8; r++)
        out[(row0 + r)*DD + d] = (xsm[r][d] - s_mu[r])*s_inv[r]*ga + be;
}

// =====================================================================
extern "C" void kernel_launch(void* const* d_in, const int* in_sizes, int n_in,
                              void* d_out, int out_size)
{
    const float* node  = (const float*)d_in[0];
    const float* pair  = (const float*)d_in[1];
    const float* rot   = (const float*)d_in[2];
    const float* trans = (const float*)d_in[3];
    const void*  maskp = (const void*) d_in[4];
    const float* Wq    = (const float*)d_in[5];
    const float* Wk    = (const float*)d_in[6];
    const float* Wv    = (const float*)d_in[7];
    const float* Wqp   = (const float*)d_in[8];
    const float* Wkp   = (const float*)d_in[9];
    const float* Wvp   = (const float*)d_in[10];
    const float* Wpb   = (const float*)d_in[11];
    const float* hw    = (const float*)d_in[12];
    const float* Wout  = (const float*)d_in[13];
    const float* bout  = (const float*)d_in[14];
    const float* gamma = (const float*)d_in[15];
    const float* beta  = (const float*)d_in[16];
    float* out = (float*)d_out;

    k_nop<<<1, 32>>>();                 // index 0
    k_nop<<<1, 32>>>();                 // index 1
    k_proj<<<dim3(NROW/8, 4), 256>>>(node, rot, trans, Wq, Wk, Wv, Wqp, Wkp, Wvp);  // index 2
    k_attn<<<dim3(LL/IT, BB*JSPLIT), 256>>>(pair, maskp, Wpb, hw);                  // index 3 <- ncu
    k_comb<<<NROW, 256>>>(rot, trans);
    k_gemm_out<<<dim3(NROW/16, KSPLIT), 256>>>(Wout);
    k_ln<<<NROW/8, 256>>>(node, bout, gamma, beta, out);
}